// round 13
// baseline (speedup 1.0000x reference)
#include <cuda_runtime.h>

#define HH 224
#define WW 224
#define NCH 64
#define BB 4

#define TH 16            // tile rows
#define TWT 32           // tile cols (2 scan halves of 16)
#define TW 16            // cols per scan thread
#define ROWSTR 376       // 47*8 floats; %32==24 -> 4-row x 8-ch warps conflict-free
#define V2RN 18          // V2 rows 6..23 stored at (r-6)
#define V8RN 24          // V8 rows 3..26 stored at (r-3)
#define SMEM_BYTES ((V2RN + V8RN) * ROWSTR * 4)

#define NPART 392        // 392*256 threads/batch * 8 float4 = exactly 224*224*64/4

// ---------------- device globals (scratch; no allocation) ----------------
__device__ float g_pmn[BB * NPART];
__device__ float g_pmx[BB * NPART];
__device__ float g_sA[BB];      // 1/(max-min+eps)
__device__ float g_xmin[BB];
__device__ float g_coef[4];     // OLS coefficients c_s
__device__ float g_bnS[NCH];    // folded BN scale
__device__ float g_bnT[NCH];    // folded BN bias

// ---------------- kernel 1: per-sample min/max partials ----------------
// Each thread: exactly 8 strided float4 loads, 8 independent acc pairs (MLP=8).
__global__ void minmaxK(const float* __restrict__ x) {
    const int b = blockIdx.y;
    const float4* xv = reinterpret_cast<const float4*>(x) + (size_t)b * (HH * WW * NCH / 4);
    const int stride = NPART * 256;
    const int i = blockIdx.x * 256 + threadIdx.x;

    float mn[8], mx[8];
    #pragma unroll
    for (int k = 0; k < 8; k++) {
        float4 v = __ldg(xv + i + k * stride);
        mn[k] = fminf(fminf(v.x, v.y), fminf(v.z, v.w));
        mx[k] = fmaxf(fmaxf(v.x, v.y), fmaxf(v.z, v.w));
    }
    #pragma unroll
    for (int k = 4; k; k >>= 1)
        #pragma unroll
        for (int j = 0; j < k; j++) {
            mn[j] = fminf(mn[j], mn[j + k]);
            mx[j] = fmaxf(mx[j], mx[j + k]);
        }
    float mnv = mn[0], mxv = mx[0];

    #pragma unroll
    for (int o = 16; o; o >>= 1) {
        mnv = fminf(mnv, __shfl_xor_sync(0xffffffffu, mnv, o));
        mxv = fmaxf(mxv, __shfl_xor_sync(0xffffffffu, mxv, o));
    }
    __shared__ float smn[8], smx[8];
    int lane = threadIdx.x & 31, wid = threadIdx.x >> 5;
    if (lane == 0) { smn[wid] = mnv; smx[wid] = mxv; }
    __syncthreads();
    if (wid == 0) {
        mnv = smn[lane & 7]; mxv = smx[lane & 7];
        #pragma unroll
        for (int o = 4; o; o >>= 1) {
            mnv = fminf(mnv, __shfl_xor_sync(0xffffffffu, mnv, o));
            mxv = fmaxf(mxv, __shfl_xor_sync(0xffffffffu, mxv, o));
        }
        if (lane == 0) {
            g_pmn[b * NPART + blockIdx.x] = mnv;
            g_pmx[b * NPART + blockIdx.x] = mxv;
        }
    }
}

// ---------------- kernel 2: finalize constants (128 threads) ----------------
__global__ void finK(const float* __restrict__ ols,
                     const float* __restrict__ gamma, const float* __restrict__ beta,
                     const float* __restrict__ mean,  const float* __restrict__ var) {
    int t = threadIdx.x;
    int lane = t & 31, w = t >> 5;      // warp w reduces batch w
    {
        float mn = 3.402823466e38f, mx = -3.402823466e38f;
        for (int k = lane; k < NPART; k += 32) {
            mn = fminf(mn, g_pmn[w * NPART + k]);
            mx = fmaxf(mx, g_pmx[w * NPART + k]);
        }
        #pragma unroll
        for (int o = 16; o; o >>= 1) {
            mn = fminf(mn, __shfl_xor_sync(0xffffffffu, mn, o));
            mx = fmaxf(mx, __shfl_xor_sync(0xffffffffu, mx, o));
        }
        if (lane == 0) {
            g_xmin[w] = mn;
            g_sA[w]   = 1.0f / (mx - mn + 1e-6f);
        }
    }
    if (t < NCH) {
        float s = gamma[t] * rsqrtf(var[t] + 1e-3f);
        g_bnS[t] = s;
        g_bnT[t] = beta[t] - mean[t] * s;
    }
    if (t == 0) {
        const float L2 = 0.69314718055994530942f;
        float wv[4], lr[4];
        float wsum = 0.f, wlr = 0.f;
        #pragma unroll
        for (int s = 0; s < 4; s++) {
            wv[s] = ols[s];
            lr[s] = (float)(s + 1) * L2;
            wsum += wv[s];
            wlr  += wv[s] * lr[s];
        }
        float lrbar = wlr / wsum;
        float den = 0.f;
        #pragma unroll
        for (int s = 0; s < 4; s++) {
            float dx = lr[s] - lrbar;
            den += wv[s] * dx * dx;
        }
        #pragma unroll
        for (int s = 0; s < 4; s++) g_coef[s] = wv[s] * (lr[s] - lrbar) / den;
    }
}

// ---------------- kernel 3: fused main (256 thr, 3 CTAs/SM = 24 warps) ----------------
__global__ void __launch_bounds__(256, 3)
mainK(const float* __restrict__ x, const float* __restrict__ anchors,
      const float* __restrict__ widths, float* __restrict__ out) {
    extern __shared__ float sm[];
    float* V2 = sm;                        // rows 6..23 at (r-6)
    float* V8 = sm + V2RN * ROWSTR;        // rows 3..26 at (r-3)

    const int tid = threadIdx.x;
    const int b  = blockIdx.z;
    const int cg = blockIdx.y;             // channel group of 8
    const int tx = blockIdx.x % (WW / TWT), ty = blockIdx.x / (WW / TWT);
    const int h0 = ty * TH, w0 = tx * TWT;
    const int gc = cg * 8;

    const float sA = g_sA[b];
    const float xmsA = -g_xmin[b] * sA;    // xs = x*sA + xmsA
    const size_t planeB = (size_t)b * HH * WW * NCH;

    // ---- phase 1: column walkers emit V2 and V8 via sliding sums ----
    // 188 walkers = 94 float4 col-slots x 2 row-halves; 19 xs rows each.
    if (tid < 188) {
        const int half = tid >= 94;
        const int slot = half ? tid - 94 : tid;   // 0..93
        const int c = slot >> 1;                  // spatial col 0..46
        const int q = slot & 1;                   // float4 half of 8ch
        const int base = half ? 12 : 0;           // first xs tile-row walked
        const int t2lo = half ? 19 : 7,  t2hi = half ? 24 : 18;
        const int t8lo = half ? 19 : 7,  t8hi = half ? 30 : 18;
        const int gw = w0 - 7 + c;
        const bool wok = (unsigned)gw < (unsigned)WW;
        const float* px = x + planeB + (size_t)gw * NCH + gc + q * 4;
        float* d2 = V2 + c * 8 + q * 4;
        float* d8 = V8 + c * 8 + q * 4;

        float4 xsr[8];
        #pragma unroll
        for (int k = 0; k < 8; k++) xsr[k] = make_float4(0.f, 0.f, 0.f, 0.f);
        float4 v8s  = make_float4(0.f, 0.f, 0.f, 0.f);
        float4 prev = make_float4(0.f, 0.f, 0.f, 0.f);

        #pragma unroll
        for (int tt = 0; tt < 19; tt++) {
            int t = base + tt;
            int gh = h0 - 7 + t;
            float4 cur = make_float4(0.f, 0.f, 0.f, 0.f);
            if (wok && (unsigned)gh < (unsigned)HH) {
                float4 v = *reinterpret_cast<const float4*>(px + (size_t)gh * (WW * NCH));
                cur = make_float4(fmaf(v.x, sA, xmsA), fmaf(v.y, sA, xmsA),
                                  fmaf(v.z, sA, xmsA), fmaf(v.w, sA, xmsA));
            }
            if (t >= t2lo && t <= t2hi)
                *reinterpret_cast<float4*>(d2 + (t - 7) * ROWSTR) =
                    make_float4(prev.x + cur.x, prev.y + cur.y,
                                prev.z + cur.z, prev.w + cur.w);
            float4 o8 = xsr[tt & 7];
            xsr[tt & 7] = cur;
            v8s.x += cur.x - o8.x; v8s.y += cur.y - o8.y;
            v8s.z += cur.z - o8.z; v8s.w += cur.w - o8.w;
            if (t >= t8lo && t <= t8hi)
                *reinterpret_cast<float4*>(d8 + (t - 7) * ROWSTR) = v8s;
            prev = cur;
        }
    }
    __syncthreads();

    // ---- phase 2: fused 4-scale scan + epilogue, one pass over 16 cols ----
    const int ch    = tid & 7;
    const int row   = (tid >> 3) & 15;     // 0..15
    const int halfc = tid >> 7;            // 0 or 1: cols 0..15 / 16..31
    const int R     = 7 + row;
    const int cofs  = halfc * 16 * 8;
    const float* p2  = V2 + (R - 6) * ROWSTR + cofs + ch;   // row R
    const float* p2a = p2 - ROWSTR;                          // row R-1
    const float* p2b = p2 + ROWSTR;                          // row R+1
    const float* p8  = V8 + (R - 3) * ROWSTR + cofs + ch;   // row R
    const float* pga = p8 - 4 * ROWSTR;                      // row R-4
    const float* pgb = p8 + 4 * ROWSTR;                      // row R+4
    const float c0 = g_coef[0], c1 = g_coef[1], c2 = g_coef[2], c3 = g_coef[3];

    // init windows (output col j=0 -> smem center col 7)
    float r2[2], r4[4], r8[8], r16[16];
    float ws2 = 0.f, ws4 = 0.f, ws8 = 0.f, ws16 = 0.f;
    #pragma unroll
    for (int k = 0; k < 2; k++)  { r2[k]  = p2[(7 + k) * 8];               ws2  += r2[k]; }
    #pragma unroll
    for (int k = 0; k < 4; k++)  { r4[k]  = p2a[(6 + k) * 8] + p2b[(6 + k) * 8]; ws4 += r4[k]; }
    #pragma unroll
    for (int k = 0; k < 8; k++)  { r8[k]  = p8[(4 + k) * 8];               ws8  += r8[k]; }
    #pragma unroll
    for (int k = 0; k < 16; k++) { r16[k] = pga[k * 8] + pgb[k * 8];       ws16 += r16[k]; }

    const int gcc = gc + ch;
    float AN[8], W8[8];
    #pragma unroll
    for (int k = 0; k < 8; k++) {
        AN[k] = __ldg(anchors + gcc * 8 + k);
        W8[k] = __ldg(widths  + gcc * 8 + k);
    }
    const float bnS = g_bnS[gcc], bnT = g_bnT[gcc];
    const int gh = h0 + row;
    const size_t base = planeB + ((size_t)gh * WW + w0 + halfc * 16) * NCH + gcc;

    #pragma unroll
    for (int j = 0; j < TW; j++) {
        float acc = c0 * __logf(ws2 + 1e-6f)
                  + c1 * __logf(ws4 + 1e-6f)
                  + c2 * __logf(ws8 + 1e-6f)
                  + c3 * __logf(ws16 + 1e-6f);
        float a = fmaf(acc, bnS, bnT);
        float t = 0.f;
        #pragma unroll
        for (int k = 0; k < 8; k++) {
            float d = fabsf(a - AN[k]);
            t += fmaxf(fmaf(-W8[k], d, 1.0f), 0.0f);
        }
        float sig = __fdividef(1.0f, 1.0f + __expf(-t));
        out[base + (size_t)j * NCH] = __ldg(x + base + (size_t)j * NCH) + sig;

        if (j < TW - 1) {
            float n2  = p2[(9 + j) * 8];
            float n4  = p2a[(10 + j) * 8] + p2b[(10 + j) * 8];
            float n8  = p8[(12 + j) * 8];
            float n16 = pga[(16 + j) * 8] + pgb[(16 + j) * 8];
            ws2  += n2  - r2[j & 1];    r2[j & 1]   = n2;
            ws4  += n4  - r4[j & 3];    r4[j & 3]   = n4;
            ws8  += n8  - r8[j & 7];    r8[j & 7]   = n8;
            ws16 += n16 - r16[j & 15];  r16[j & 15] = n16;
        }
    }
}

// ---------------- launch ----------------
extern "C" void kernel_launch(void* const* d_in, const int* in_sizes, int n_in,
                              void* d_out, int out_size) {
    const float* x       = (const float*)d_in[0];
    const float* ols     = (const float*)d_in[1];
    const float* anchors = (const float*)d_in[2];
    const float* widths  = (const float*)d_in[3];
    const float* gamma   = (const float*)d_in[4];
    const float* beta    = (const float*)d_in[5];
    const float* mean    = (const float*)d_in[6];
    const float* var     = (const float*)d_in[7];
    float* out = (float*)d_out;

    cudaFuncSetAttribute(mainK, cudaFuncAttributeMaxDynamicSharedMemorySize, SMEM_BYTES);

    minmaxK<<<dim3(NPART, BB), 256>>>(x);
    finK<<<1, 128>>>(ols, gamma, beta, mean, var);
    mainK<<<dim3((WW / TWT) * (HH / TH), 8, BB), 256, SMEM_BYTES>>>(x, anchors, widths, out);
}